// round 15
// baseline (speedup 1.0000x reference)
#include <cuda_runtime.h>
#include <math.h>
#include <stdint.h>

namespace {
constexpr int CL = 18, X = 200, Y = 200, Z = 16;
constexpr int Xd = 100, Yd = 100, Zd = 16;
constexpr int NV = Xd * Yd * Zd;      // 160000
constexpr int NCOLS = Xd * Yd;        // 10000
constexpr int NVF = X * Y * Z;        // 640000
}

// ---------------- packed fp32x2 helpers ------------------------------------
__device__ __forceinline__ uint64_t pack2(float a, float b) {
    uint64_t r; asm("mov.b64 %0, {%1, %2};" : "=l"(r) : "f"(a), "f"(b)); return r;
}
__device__ __forceinline__ uint64_t dup2(float a) {
    uint64_t r; asm("mov.b64 %0, {%1, %1};" : "=l"(r) : "f"(a)); return r;
}
__device__ __forceinline__ void ffma2(uint64_t& d, uint64_t a, uint64_t b) {
    asm("fma.rn.f32x2 %0, %1, %2, %0;" : "+l"(d) : "l"(a), "l"(b));
}
__device__ __forceinline__ float2 unpack2(uint64_t v) {
    float2 r; asm("mov.b64 {%0, %1}, %2;" : "=f"(r.x), "=f"(r.y) : "l"(v)); return r;
}
__device__ __forceinline__ float lo2(uint64_t v) {
    float a, b; asm("mov.b64 {%0, %1}, %2;" : "=f"(a), "=f"(b) : "l"(v)); return a;
}
__device__ __forceinline__ float hi2(uint64_t v) {
    float a, b; asm("mov.b64 {%0, %1}, %2;" : "=f"(a), "=f"(b) : "l"(v)); return b;
}
__device__ __forceinline__ void ffma_lo(uint64_t& d, float a, float b) {
    asm("{\n\t.reg .f32 lo, hi;\n\tmov.b64 {lo, hi}, %0;\n\t"
        "fma.rn.f32 lo, %1, %2, lo;\n\tmov.b64 %0, {lo, hi};\n\t}"
        : "+l"(d) : "f"(a), "f"(b));
}
__device__ __forceinline__ void ffma_hi(uint64_t& d, float a, float b) {
    asm("{\n\t.reg .f32 lo, hi;\n\tmov.b64 {lo, hi}, %0;\n\t"
        "fma.rn.f32 hi, %1, %2, hi;\n\tmov.b64 %0, {lo, hi};\n\t}"
        : "+l"(d) : "f"(a), "f"(b));
}
__device__ __forceinline__ float tanh_ap(float x) {
    float y; asm("tanh.approx.f32 %0, %1;" : "=f"(y) : "f"(x)); return y;
}

// ------------------------- device-global scratch ---------------------------
__device__ float d_fast[4 * 64 * NV];
__device__ float d_z[64 * NV];
__device__ float d_zw[64 * NV];
__device__ float d_fadv[64 * NV];
__device__ float d_dX[64 * NV];
__device__ float d_k1[64 * NV];
__device__ float d_h[32 * NV];
__device__ float d_h2[32 * NV];
__device__ float d_c[32 * NV];
__device__ float d_c2[32 * NV];
__device__ float d_tinv[3][12];
__device__ float d_dtau[3];
__device__ float d_gsum[19 * 8];
__device__ float d_gss[19 * 8];
__device__ float4 d_wfe4[18 * 9 * 64];
__device__ float4 d_wse4[18 * 9 * 64];
__device__ float4 d_wbA[3][288 * 16];
__device__ float2 d_wbB[3][288 * 16];
__device__ float4 d_wdecv[4 * 64 * 4 * 18];
__device__ float d_wctrl[65 * 64];
__device__ float d_wgin[128 * 32];
__device__ float d_wgout[32 * 64];

// --------------- one fused prep kernel: repacks + GN accumulator reset -----
__global__ void k_prep(const float* __restrict__ fe, const float* __restrict__ se,
                       const float* __restrict__ gb, const float* __restrict__ dec,
                       const float* __restrict__ ctrl, const float* __restrict__ gin,
                       const float* __restrict__ gout) {
    int i = blockIdx.x * 256 + threadIdx.x;
    if (i < 152) { d_gsum[i] = 0.f; d_gss[i] = 0.f; }
    if (i < 10368) {
        int ci = i / 576; int r = i - ci * 576; int dd = r >> 6; int co = r & 63;
        const float* s = fe + co * 486 + ci * 27 + dd * 3;
        d_wfe4[i] = make_float4(s[0], s[1], s[2], 0.f); return;
    }
    i -= 10368;
    if (i < 10368) {
        int ci = i / 576; int r = i - ci * 576; int dd = r >> 6; int co = r & 63;
        const float* s = se + co * 486 + ci * 27 + dd * 3;
        d_wse4[i] = make_float4(s[0], s[1], s[2], 0.f); return;
    }
    i -= 10368;
    if (i < 3 * 4608) {
        int lay = i / 4608; int u = i - lay * 4608;
        int t = u >> 4, p = u & 15;
        int ci = t / 9, tap = t - ci * 9;
        const float* g0 = gb + lay * 27648 + (2 * p) * 864 + ci * 27 + tap * 3;
        const float* g1 = g0 + 864;
        d_wbA[lay][u] = make_float4(g0[0], g1[0], g0[1], g1[1]);
        d_wbB[lay][u] = make_float2(g0[2], g1[2]);
        return;
    }
    i -= 3 * 4608;
    if (i < 18432) {
        int par = i / 4608; int r = i - par * 4608;
        int ci = r / 72; int r2 = r - ci * 72;
        int tap = r2 / 18; int co = r2 - tap * 18;
        int du = tap >> 1, dv = tap & 1;
        int px = par >> 1, py = par & 1;
        float s0 = 0.f, s1 = 0.f, s2 = 0.f;
        for (int kx = 0; kx < 3; kx++) {
            bool okx = (px == 0) ? (du == 0 ? (kx == 0) : (kx >= 1))
                                 : (du == 0 ? (kx <= 1) : (kx == 2));
            if (!okx) continue;
            for (int ky = 0; ky < 3; ky++) {
                bool oky = (py == 0) ? (dv == 0 ? (ky == 0) : (ky >= 1))
                                     : (dv == 0 ? (ky <= 1) : (ky == 2));
                if (!oky) continue;
                const float* s = dec + (((co * 64 + ci) * 3 + kx) * 3 + ky) * 3;
                s0 += s[0]; s1 += s[1]; s2 += s[2];
            }
        }
        d_wdecv[i] = make_float4(s0, s1, s2, 0.f);
        return;
    }
    i -= 18432;
    if (i < 4160) { int j = i >> 6, co = i & 63; d_wctrl[j * 64 + co] = ctrl[co * 65 + j]; return; }
    i -= 4160;
    if (i < 4096) { int j = i >> 5, co = i & 31; d_wgin[j * 32 + co] = gin[co * 128 + j]; return; }
    i -= 4096;
    if (i < 2048) { int j = i >> 6, co = i & 63; d_wgout[j * 64 + co] = gout[co * 32 + j]; return; }
}

// --------- per-step transforms: tinv = inv(pose[k]) @ pose[k+1], dtau ------
__global__ void k_transforms(const float* __restrict__ pose, const int* __restrict__ ts) {
    if (threadIdx.x != 0 || blockIdx.x != 0) return;
    for (int k = 0; k < 3; k++) {
        float A[4][4], Iv[4][4];
        for (int r = 0; r < 4; r++)
            for (int c = 0; c < 4; c++) {
                A[r][c] = pose[k * 16 + r * 4 + c];
                Iv[r][c] = (r == c) ? 1.f : 0.f;
            }
        for (int c = 0; c < 4; c++) {
            int piv = c;
            for (int r = c + 1; r < 4; r++)
                if (fabsf(A[r][c]) > fabsf(A[piv][c])) piv = r;
            if (piv != c)
                for (int j = 0; j < 4; j++) {
                    float t = A[c][j]; A[c][j] = A[piv][j]; A[piv][j] = t;
                    t = Iv[c][j]; Iv[c][j] = Iv[piv][j]; Iv[piv][j] = t;
                }
            float dinv = 1.f / A[c][c];
            for (int j = 0; j < 4; j++) { A[c][j] *= dinv; Iv[c][j] *= dinv; }
            for (int r = 0; r < 4; r++) {
                if (r == c) continue;
                float f = A[r][c];
                for (int j = 0; j < 4; j++) { A[r][j] -= f * A[c][j]; Iv[r][j] -= f * Iv[c][j]; }
            }
        }
        const float* B = pose + (k + 1) * 16;
        for (int r = 0; r < 3; r++)
            for (int c = 0; c < 4; c++) {
                float s = 0.f;
                for (int j = 0; j < 4; j++) s += Iv[r][j] * B[j * 4 + c];
                d_tinv[k][r * 4 + c] = s;
            }
        d_dtau[k] = (float)(ts[k + 1] - ts[k]) * 1e-6f;
    }
}

// -------- encoder conv 18->64, 3x3x3, stride (2,2,1), pad 1, ReLU ----------
__global__ void __launch_bounds__(128) k_enc(const float* __restrict__ inbase,
                                             const float4* __restrict__ wq,
                                             const float* __restrict__ b,
                                             float* __restrict__ outbase,
                                             const float* __restrict__ subsrc) {
    __shared__ __align__(16) float patch[2 * 162 * 24];
    const float* in = inbase + (size_t)blockIdx.y * CL * NVF;
    float* out = outbase + (size_t)blockIdx.y * 64 * NV;
    int tid = threadIdx.x;
    int p0 = blockIdx.x * 2;
    for (int u = tid; u < 324; u += 128) {
        int lc = u / 162; int r = u - lc * 162; int ci = r / 9; int dd = r - ci * 9;
        int p = p0 + lc; int x = p / Yd, y = p - x * Yd;
        int ix = 2 * x - 1 + dd / 3, iy = 2 * y - 1 + dd % 3;
        float* col = patch + u * 24;
        if ((unsigned)ix < (unsigned)X && (unsigned)iy < (unsigned)Y) {
            const float4* g = (const float4*)(in + ((size_t)(ci * X + ix) * Y + iy) * Z);
            float4 a0 = g[0], a1 = g[1], a2 = g[2], a3 = g[3];
            col[0] = 0.f;
            col[1] = a0.x; col[2] = a0.y; col[3] = a0.z; col[4] = a0.w;
            col[5] = a1.x; col[6] = a1.y; col[7] = a1.z; col[8] = a1.w;
            col[9] = a2.x; col[10] = a2.y; col[11] = a2.z; col[12] = a2.w;
            col[13] = a3.x; col[14] = a3.y; col[15] = a3.z; col[16] = a3.w;
            col[17] = 0.f;
        } else {
            float4 zz = make_float4(0.f, 0.f, 0.f, 0.f);
            float4* c4 = (float4*)col;
            c4[0] = zz; c4[1] = zz; c4[2] = zz; c4[3] = zz;
            col[16] = 0.f; col[17] = 0.f;
        }
    }
    __syncthreads();
    int lc = tid >> 6, c = tid & 63;
    float bb = __ldg(&b[c]);
    uint64_t acc[8];
    uint64_t binit = dup2(bb);
#pragma unroll
    for (int i = 0; i < 8; i++) acc[i] = binit;
    const float* pb = patch + lc * 162 * 24;
#pragma unroll 1
    for (int ci = 0; ci < 18; ci++) {
#pragma unroll
        for (int dd = 0; dd < 9; dd++) {
            const float* col = pb + (ci * 9 + dd) * 24;
            const ulonglong2* v2 = (const ulonglong2*)col;
            uint64_t pe[9];
            ulonglong2 t0 = v2[0], t1 = v2[1], t2 = v2[2], t3 = v2[3];
            pe[0] = t0.x; pe[1] = t0.y; pe[2] = t1.x; pe[3] = t1.y;
            pe[4] = t2.x; pe[5] = t2.y; pe[6] = t3.x; pe[7] = t3.y;
            pe[8] = ((const uint64_t*)col)[8];
            float4 w = __ldg(&wq[(ci * 9 + dd) * 64 + c]);
            uint64_t w0 = dup2(w.x), w2 = dup2(w.z);
#pragma unroll
            for (int i = 0; i < 8; i++) ffma2(acc[i], pe[i], w0);
#pragma unroll
            for (int i = 0; i < 8; i++) {
                ffma_lo(acc[i], hi2(pe[i]), w.y);
                ffma_hi(acc[i], lo2(pe[i + 1]), w.y);
            }
#pragma unroll
            for (int i = 0; i < 8; i++) ffma2(acc[i], pe[i + 1], w2);
        }
    }
    size_t obase = (size_t)c * NV + (size_t)(p0 + lc) * 16;
    float* op = out + obase;
    float4* o4 = (float4*)op;
    if (subsrc) {
        const float4* s4 = (const float4*)(subsrc + obase);
#pragma unroll
        for (int q = 0; q < 4; q++) {
            float2 u0 = unpack2(acc[2 * q]);
            float2 u1 = unpack2(acc[2 * q + 1]);
            float4 sv = s4[q];
            o4[q] = make_float4(fmaxf(u0.x, 0.f) - sv.x, fmaxf(u0.y, 0.f) - sv.y,
                                fmaxf(u1.x, 0.f) - sv.z, fmaxf(u1.y, 0.f) - sv.w);
        }
    } else {
#pragma unroll
        for (int q = 0; q < 4; q++) {
            float2 u0 = unpack2(acc[2 * q]);
            float2 u1 = unpack2(acc[2 * q + 1]);
            o4[q] = make_float4(fmaxf(u0.x, 0.f), fmaxf(u0.y, 0.f), fmaxf(u1.x, 0.f), fmaxf(u1.y, 0.f));
        }
    }
}

// ------- fused warp + ctrl: zw/fadv trilinear warp AND dX GEMV in one pass --
__global__ void __launch_bounds__(256) k_warpctrl(const float* __restrict__ zin,
                                                  const float* __restrict__ fin,
                                                  const float* __restrict__ ft,
                                                  const float* __restrict__ wt,
                                                  const float* __restrict__ b,
                                                  float* __restrict__ zw,
                                                  float* __restrict__ fadv,
                                                  float* __restrict__ dX, int step) {
    __shared__ __align__(16) float w[65 * 64 + 64];
    int tid = threadIdx.x;
    for (int i = tid; i < 65 * 64; i += 256) w[i] = wt[i];
    if (tid < 64) w[65 * 64 + tid] = b[tid];
    __syncthreads();
    const uint64_t* w64 = (const uint64_t*)w;
    const uint64_t* b64 = (const uint64_t*)(w + 65 * 64);
    int v = blockIdx.x * 256 + tid;
    int p = v >> 4, z = v & 15;
    int x = p / Yd, y = p - x * Yd;
    float wxw = -40.f + (x + 0.5f) * 0.8f;
    float wyw = -40.f + (y + 0.5f) * 0.8f;
    float wzw = -1.f + (z + 0.5f) * 0.4f;
    const float* M = d_tinv[step];
    float px = M[0] * wxw + M[1] * wyw + M[2] * wzw + M[3];
    float py = M[4] * wxw + M[5] * wyw + M[6] * wzw + M[7];
    float pz = M[8] * wxw + M[9] * wyw + M[10] * wzw + M[11];
    float gxf = (px + 40.f) / 0.8f - 0.5f;
    float gyf = (py + 40.f) / 0.8f - 0.5f;
    float gzf = (pz + 1.f) / 0.4f - 0.5f;
    gxf = fminf(fmaxf(gxf, 0.f), 99.f);
    gyf = fminf(fmaxf(gyf, 0.f), 99.f);
    gzf = fminf(fmaxf(gzf, 0.f), 15.f);
    float fx0 = floorf(gxf), fy0 = floorf(gyf), fz0 = floorf(gzf);
    int x0 = (int)fx0, y0 = (int)fy0, z0 = (int)fz0;
    int x1 = min(x0 + 1, 99), y1 = min(y0 + 1, 99), z1 = min(z0 + 1, 15);
    float fx = gxf - fx0, fy = gyf - fy0, fz = gzf - fz0;
    float cx0 = 1.f - fx, cy0 = 1.f - fy, cz0 = 1.f - fz;
    float w000 = cx0 * cy0 * cz0, w100 = fx * cy0 * cz0, w010 = cx0 * fy * cz0, w110 = fx * fy * cz0;
    float w001 = cx0 * cy0 * fz, w101 = fx * cy0 * fz, w011 = cx0 * fy * fz, w111 = fx * fy * fz;
    int o00 = (x0 * Yd + y0) * Zd, o01 = (x0 * Yd + y1) * Zd;
    int o10 = (x1 * Yd + y0) * Zd, o11 = (x1 * Yd + y1) * Zd;
    uint64_t acc[32];
#pragma unroll
    for (int j = 0; j < 32; j++) acc[j] = b64[j];
#pragma unroll 2
    for (int c = 0; c < 64; c++) {
        const float* a = zin + c * NV;
        float r = __ldg(a + o00 + z0) * w000 + __ldg(a + o10 + z0) * w100
                + __ldg(a + o01 + z0) * w010 + __ldg(a + o11 + z0) * w110
                + __ldg(a + o00 + z1) * w001 + __ldg(a + o10 + z1) * w101
                + __ldg(a + o01 + z1) * w011 + __ldg(a + o11 + z1) * w111;
        zw[c * NV + v] = r;
        const float* f = fin + c * NV;
        float r2 = __ldg(f + o00 + z0) * w000 + __ldg(f + o10 + z0) * w100
                 + __ldg(f + o01 + z0) * w010 + __ldg(f + o11 + z0) * w110
                 + __ldg(f + o00 + z1) * w001 + __ldg(f + o10 + z1) * w101
                 + __ldg(f + o01 + z1) * w011 + __ldg(f + o11 + z1) * w111;
        fadv[c * NV + v] = r2;
        float val = __ldg(&ft[c * NV + v]) - r2;
        uint64_t vd = dup2(val);
#pragma unroll
        for (int j = 0; j < 32; j++) ffma2(acc[j], w64[c * 32 + j], vd);
    }
    {
        uint64_t vd = dup2(d_dtau[step]);
#pragma unroll
        for (int j = 0; j < 32; j++) ffma2(acc[j], w64[64 * 32 + j], vd);
    }
#pragma unroll
    for (int j = 0; j < 32; j++) {
        float2 u = unpack2(acc[j]);
        dX[(2 * j) * NV + v] = u.x;
        dX[(2 * j + 1) * NV + v] = u.y;
    }
}

// ------- g_in: h = relu(W(32x128)[A(+A2); B] + b), 2 voxels per thread -----
__global__ void __launch_bounds__(128) k_gin(const float* __restrict__ A, const float* __restrict__ A2,
                                             const float* __restrict__ B, const float* __restrict__ wt,
                                             const float* __restrict__ b, float* __restrict__ h) {
    __shared__ __align__(16) float w[128 * 32 + 32];
    int tid = threadIdx.x;
    for (int i = tid; i < 128 * 32; i += 128) w[i] = wt[i];
    if (tid < 32) w[128 * 32 + tid] = b[tid];
    __syncthreads();
    const uint64_t* w64 = (const uint64_t*)w;
    const uint64_t* b64 = (const uint64_t*)(w + 128 * 32);
    int v = (blockIdx.x * 128 + tid) * 2;
    uint64_t acc0[16], acc1[16];
#pragma unroll
    for (int j = 0; j < 16; j++) { acc0[j] = b64[j]; acc1[j] = b64[j]; }
#pragma unroll 1
    for (int ci = 0; ci < 64; ci++) {
        float2 a = *(const float2*)(A + ci * NV + v);
        if (A2) {
            float2 a2 = *(const float2*)(A2 + ci * NV + v);
            a.x += a2.x; a.y += a2.y;
        }
        uint64_t vd0 = dup2(a.x), vd1 = dup2(a.y);
#pragma unroll
        for (int j = 0; j < 16; j++) {
            uint64_t ww = w64[ci * 16 + j];
            ffma2(acc0[j], ww, vd0);
            ffma2(acc1[j], ww, vd1);
        }
    }
#pragma unroll 1
    for (int ci = 64; ci < 128; ci++) {
        float2 a = *(const float2*)(B + (ci - 64) * NV + v);
        uint64_t vd0 = dup2(a.x), vd1 = dup2(a.y);
#pragma unroll
        for (int j = 0; j < 16; j++) {
            uint64_t ww = w64[ci * 16 + j];
            ffma2(acc0[j], ww, vd0);
            ffma2(acc1[j], ww, vd1);
        }
    }
#pragma unroll
    for (int j = 0; j < 16; j++) {
        float2 u0 = unpack2(acc0[j]);
        float2 u1 = unpack2(acc1[j]);
        *(float2*)&h[(2 * j) * NV + v] = make_float2(fmaxf(u0.x, 0.f), fmaxf(u1.x, 0.f));
        *(float2*)&h[(2 * j + 1) * NV + v] = make_float2(fmaxf(u0.y, 0.f), fmaxf(u1.y, 0.f));
    }
}

// ------- dilated body conv 32->32, 3x3x3, dil D ----------------------------
template <int D>
__global__ void __launch_bounds__(128, 7) k_body(const float* __restrict__ hin,
                                                 const float* __restrict__ gnc,
                                                 float* __restrict__ hwb,
                                                 const float* __restrict__ gsc,
                                                 const float* __restrict__ gbi,
                                                 int gn_inst,
                                                 const float4* __restrict__ wA,
                                                 const float2* __restrict__ wB,
                                                 const float* __restrict__ b,
                                                 float* __restrict__ cout, int inst) {
    extern __shared__ __align__(16) float patch[];
    constexpr int STRIDE = (D == 3) ? 24 : 20;
    constexpr int SY = 8 + 2 * D;
    constexpr int NU = 3 * 8 * SY;
    __shared__ float gsh[8], gqh[8];
    int tid = threadIdx.x;
    if (tid < 8) { gsh[tid] = 0.f; gqh[tid] = 0.f; }
    int bx = blockIdx.x;
    int x = bx / 13; int ty = bx - x * 13; int y0 = ty * 8;
    int w = tid >> 5, l = tid & 31;
    int hh = l >> 4, p = l & 15;
    int cyl = 2 * w + hh;
    int colY = y0 + cyl;
    bool act = (y0 + 2 * w < 100);
    int coA = 2 * p, coB = coA + 1;
    uint64_t accA[8], accB[8];
    uint64_t bia = dup2(__ldg(&b[coA])), bib = dup2(__ldg(&b[coB]));
#pragma unroll
    for (int i = 0; i < 8; i++) { accA[i] = bia; accB[i] = bib; }
    constexpr int NPE = 8 + D;
    const float ginv = 1.f / (4.f * (float)NV);
#pragma unroll 1
    for (int s = 0; s < 4; s++) {
        for (int u = tid; u < NU; u += 128) {
            int kx = u / (8 * SY); int r = u - kx * (8 * SY);
            int cis = r / SY; int iyi = r - cis * SY;
            int ci = 8 * s + cis;
            int ix = x + (kx - 1) * D, iy = y0 - D + iyi;
            float* col = patch + u * STRIDE;
            if ((unsigned)ix < (unsigned)Xd && (unsigned)iy < (unsigned)Yd) {
                size_t off = (size_t)ci * NV + (ix * Yd + iy) * Zd;
                const float4* g = (const float4*)(hin + off);
                float4 a0 = g[0], a1 = g[1], a2 = g[2], a3 = g[3];
                if (gnc) {
                    int gg = ci >> 2;
                    float m = d_gsum[gn_inst * 8 + gg] * ginv;
                    float var = d_gss[gn_inst * 8 + gg] * ginv - m * m;
                    float rr = rsqrtf(var + 1e-5f);
                    float sc = __ldg(&gsc[ci]) * rr;
                    float bi = __ldg(&gbi[ci]) - m * sc;
                    const float4* gc = (const float4*)(gnc + off);
                    float4 c0 = gc[0], c1 = gc[1], c2 = gc[2], c3 = gc[3];
                    a0.x += fmaxf(c0.x * sc + bi, 0.f); a0.y += fmaxf(c0.y * sc + bi, 0.f);
                    a0.z += fmaxf(c0.z * sc + bi, 0.f); a0.w += fmaxf(c0.w * sc + bi, 0.f);
                    a1.x += fmaxf(c1.x * sc + bi, 0.f); a1.y += fmaxf(c1.y * sc + bi, 0.f);
                    a1.z += fmaxf(c1.z * sc + bi, 0.f); a1.w += fmaxf(c1.w * sc + bi, 0.f);
                    a2.x += fmaxf(c2.x * sc + bi, 0.f); a2.y += fmaxf(c2.y * sc + bi, 0.f);
                    a2.z += fmaxf(c2.z * sc + bi, 0.f); a2.w += fmaxf(c2.w * sc + bi, 0.f);
                    a3.x += fmaxf(c3.x * sc + bi, 0.f); a3.y += fmaxf(c3.y * sc + bi, 0.f);
                    a3.z += fmaxf(c3.z * sc + bi, 0.f); a3.w += fmaxf(c3.w * sc + bi, 0.f);
                    float4* hw = (float4*)(hwb + off);
                    hw[0] = a0; hw[1] = a1; hw[2] = a2; hw[3] = a3;
                }
#pragma unroll
                for (int j = 0; j < D; j++) col[j] = 0.f;
                col[D + 0] = a0.x; col[D + 1] = a0.y; col[D + 2] = a0.z; col[D + 3] = a0.w;
                col[D + 4] = a1.x; col[D + 5] = a1.y; col[D + 6] = a1.z; col[D + 7] = a1.w;
                col[D + 8] = a2.x; col[D + 9] = a2.y; col[D + 10] = a2.z; col[D + 11] = a2.w;
                col[D + 12] = a3.x; col[D + 13] = a3.y; col[D + 14] = a3.z; col[D + 15] = a3.w;
#pragma unroll
                for (int j = D + 16; j < 16 + 2 * D; j++) col[j] = 0.f;
            } else {
                float4 zz = make_float4(0.f, 0.f, 0.f, 0.f);
                float4* c4 = (float4*)col;
#pragma unroll
                for (int j = 0; j < STRIDE / 4; j++) c4[j] = zz;
            }
        }
        __syncthreads();
        if (act) {
#pragma unroll 1
            for (int cis = 0; cis < 8; cis++) {
#pragma unroll
                for (int kx = 0; kx < 3; kx++) {
#pragma unroll
                    for (int ky = 0; ky < 3; ky++) {
                        const float* col = patch + (((kx * 8 + cis) * SY) + cyl + ky * D) * STRIDE;
                        uint64_t pe[11];
                        const ulonglong2* v2 = (const ulonglong2*)col;
#pragma unroll
                        for (int q = 0; q < NPE / 2; q++) {
                            ulonglong2 t = v2[q];
                            pe[2 * q] = t.x; pe[2 * q + 1] = t.y;
                        }
                        if constexpr (NPE & 1) pe[NPE - 1] = ((const uint64_t*)col)[NPE - 1];
                        int widx = ((8 * s + cis) * 9 + kx * 3 + ky) * 16 + p;
                        float4 wa = __ldg(&wA[widx]);
                        float2 wb = __ldg(&wB[widx]);
                        uint64_t w0a = dup2(wa.x), w0b = dup2(wa.y);
                        uint64_t w2a = dup2(wb.x), w2b = dup2(wb.y);
#pragma unroll
                        for (int i = 0; i < 8; i++) { ffma2(accA[i], pe[i], w0a); ffma2(accB[i], pe[i], w0b); }
                        if constexpr ((D & 1) == 0) {
                            uint64_t w1a = dup2(wa.z), w1b = dup2(wa.w);
#pragma unroll
                            for (int i = 0; i < 8; i++) {
                                ffma2(accA[i], pe[i + D / 2], w1a);
                                ffma2(accB[i], pe[i + D / 2], w1b);
                            }
                        } else {
                            uint64_t w1a = dup2(wa.z), w1b = dup2(wa.w);
#pragma unroll
                            for (int i = 0; i < 8; i++) {
                                uint64_t sh = pack2(hi2(pe[i + (D - 1) / 2]), lo2(pe[i + (D + 1) / 2]));
                                ffma2(accA[i], sh, w1a);
                                ffma2(accB[i], sh, w1b);
                            }
                        }
#pragma unroll
                        for (int i = 0; i < 8; i++) { ffma2(accA[i], pe[i + D], w2a); ffma2(accB[i], pe[i + D], w2b); }
                    }
                }
            }
        }
        __syncthreads();
    }
    if (act) {
        float s = 0.f, ss = 0.f;
        size_t cb = (size_t)(x * Yd + colY) * 16;
        float4* oA = (float4*)(cout + (size_t)coA * NV + cb);
        float4* oB = (float4*)(cout + (size_t)coB * NV + cb);
#pragma unroll
        for (int q = 0; q < 4; q++) {
            float2 a0 = unpack2(accA[2 * q]);
            float2 a1 = unpack2(accA[2 * q + 1]);
            s += a0.x + a0.y + a1.x + a1.y;
            ss += a0.x * a0.x + a0.y * a0.y + a1.x * a1.x + a1.y * a1.y;
            oA[q] = make_float4(a0.x, a0.y, a1.x, a1.y);
            float2 b0 = unpack2(accB[2 * q]);
            float2 b1 = unpack2(accB[2 * q + 1]);
            s += b0.x + b0.y + b1.x + b1.y;
            ss += b0.x * b0.x + b0.y * b0.y + b1.x * b1.x + b1.y * b1.y;
            oB[q] = make_float4(b0.x, b0.y, b1.x, b1.y);
        }
        atomicAdd(&gsh[p >> 1], s);
        atomicAdd(&gqh[p >> 1], ss);
    }
    __syncthreads();
    if (tid < 8) {
        atomicAdd(&d_gsum[inst * 8 + tid], gsh[tid]);
        atomicAdd(&d_gss[inst * 8 + tid], gqh[tid]);
    }
}

// ---- gout(pass0, GN2-fused) + gin(pass1) fused:  k1 = tanh(Wg.hin_eff)*dX;
//      h' = relu(Wgin[zw + k1 ; ft] + b)  -----------------------------------
__global__ void __launch_bounds__(256) k_goutgin(const float* __restrict__ h, const float* __restrict__ wt,
                                                 const float* __restrict__ b, const float* __restrict__ dX,
                                                 const float* __restrict__ cbuf, const float* __restrict__ gsc,
                                                 const float* __restrict__ gbi, int inst,
                                                 const float* __restrict__ zw, const float* __restrict__ ft,
                                                 const float* __restrict__ wg, const float* __restrict__ bg,
                                                 float* __restrict__ k1out, float* __restrict__ hout) {
    __shared__ __align__(16) float w[32 * 64 + 64 + 64 + 128 * 32 + 32];
    int tid = threadIdx.x;
    for (int i = tid; i < 32 * 64; i += 256) w[i] = wt[i];
    if (tid < 64) w[32 * 64 + tid] = b[tid];
    if (tid < 32) w[32 * 64 + 64 + tid] = __ldg(&gsc[tid]);
    if (tid >= 32 && tid < 64) w[32 * 64 + 64 + tid] = __ldg(&gbi[tid - 32]);
    float* wgs = w + 32 * 64 + 64 + 64;
    for (int i = tid; i < 128 * 32; i += 256) wgs[i] = wg[i];
    if (tid < 32) wgs[128 * 32 + tid] = bg[tid];
    __syncthreads();
    const uint64_t* w64 = (const uint64_t*)w;
    const uint64_t* b64 = (const uint64_t*)(w + 32 * 64);
    const float* scv = w + 32 * 64 + 64;
    const float* biv = scv + 32;
    const uint64_t* wg64 = (const uint64_t*)wgs;
    const uint64_t* bg64 = (const uint64_t*)(wgs + 128 * 32);
    float mg[8], rg[8];
    float inv = 1.f / (4.f * (float)NV);
#pragma unroll
    for (int g = 0; g < 8; g++) {
        float m = d_gsum[inst * 8 + g] * inv;
        float var = d_gss[inst * 8 + g] * inv - m * m;
        mg[g] = m;
        rg[g] = rsqrtf(var + 1e-5f);
    }
    int v = blockIdx.x * 256 + tid;
    uint64_t acc[32];
#pragma unroll
    for (int j = 0; j < 32; j++) acc[j] = b64[j];
#pragma unroll 1
    for (int ci = 0; ci < 32; ci++) {
        int g = ci >> 2;
        float cv = cbuf[ci * NV + v];
        float gnv = fmaxf((cv - mg[g]) * rg[g] * scv[ci] + biv[ci], 0.f);
        float val = h[ci * NV + v] + gnv;
        uint64_t vd = dup2(val);
#pragma unroll
        for (int j = 0; j < 32; j++) ffma2(acc[j], w64[ci * 32 + j], vd);
    }
    uint64_t gacc[16];
#pragma unroll
    for (int j = 0; j < 16; j++) gacc[j] = bg64[j];
#pragma unroll 1
    for (int j = 0; j < 32; j++) {
        float2 u = unpack2(acc[j]);
        int i0 = (2 * j) * NV + v, i1 = (2 * j + 1) * NV + v;
        float t0 = tanh_ap(u.x) * dX[i0];
        float t1 = tanh_ap(u.y) * dX[i1];
        k1out[i0] = t0;
        k1out[i1] = t1;
        float a0 = zw[i0] + t0;
        float a1 = zw[i1] + t1;
        uint64_t vd0 = dup2(a0), vd1 = dup2(a1);
#pragma unroll
        for (int jj = 0; jj < 16; jj++) {
            ffma2(gacc[jj], wg64[(2 * j) * 16 + jj], vd0);
            ffma2(gacc[jj], wg64[(2 * j + 1) * 16 + jj], vd1);
        }
    }
#pragma unroll 1
    for (int c = 64; c < 128; c++) {
        float val = __ldg(&ft[(c - 64) * NV + v]);
        uint64_t vd = dup2(val);
#pragma unroll
        for (int jj = 0; jj < 16; jj++) ffma2(gacc[jj], wg64[c * 16 + jj], vd);
    }
#pragma unroll
    for (int jj = 0; jj < 16; jj++) {
        float2 u = unpack2(gacc[jj]);
        hout[(2 * jj) * NV + v] = fmaxf(u.x, 0.f);
        hout[(2 * jj + 1) * NV + v] = fmaxf(u.y, 0.f);
    }
}

// ---- g_out pass1 (GN2-fused, Heun z update) -------------------------------
__global__ void __launch_bounds__(256) k_gout(const float* __restrict__ h, const float* __restrict__ wt,
                                              const float* __restrict__ b, const float* __restrict__ dX,
                                              const float* __restrict__ cbuf, const float* __restrict__ gsc,
                                              const float* __restrict__ gbi, int inst,
                                              const float* __restrict__ zw,
                                              const float* __restrict__ k1in, float* __restrict__ zout) {
    __shared__ __align__(16) float w[32 * 64 + 64 + 64];
    int tid = threadIdx.x;
    for (int i = tid; i < 32 * 64; i += 256) w[i] = wt[i];
    if (tid < 64) w[32 * 64 + tid] = b[tid];
    if (tid < 32) w[32 * 64 + 64 + tid] = __ldg(&gsc[tid]);
    if (tid >= 32 && tid < 64) w[32 * 64 + 64 + tid] = __ldg(&gbi[tid - 32]);
    __syncthreads();
    const uint64_t* w64 = (const uint64_t*)w;
    const uint64_t* b64 = (const uint64_t*)(w + 32 * 64);
    const float* scv = w + 32 * 64 + 64;
    const float* biv = scv + 32;
    float mg[8], rg[8];
    float inv = 1.f / (4.f * (float)NV);
#pragma unroll
    for (int g = 0; g < 8; g++) {
        float m = d_gsum[inst * 8 + g] * inv;
        float var = d_gss[inst * 8 + g] * inv - m * m;
        mg[g] = m;
        rg[g] = rsqrtf(var + 1e-5f);
    }
    int v = blockIdx.x * 256 + tid;
    uint64_t acc[32];
#pragma unroll
    for (int j = 0; j < 32; j++) acc[j] = b64[j];
#pragma unroll 1
    for (int ci = 0; ci < 32; ci++) {
        int g = ci >> 2;
        float cv = cbuf[ci * NV + v];
        float gnv = fmaxf((cv - mg[g]) * rg[g] * scv[ci] + biv[ci], 0.f);
        float val = h[ci * NV + v] + gnv;
        uint64_t vd = dup2(val);
#pragma unroll
        for (int j = 0; j < 32; j++) ffma2(acc[j], w64[ci * 32 + j], vd);
    }
#pragma unroll 1
    for (int j = 0; j < 32; j++) {
        float2 u = unpack2(acc[j]);
        int i0 = (2 * j) * NV + v, i1 = (2 * j + 1) * NV + v;
        float t0 = tanh_ap(u.x) * dX[i0];
        float t1 = tanh_ap(u.y) * dX[i1];
        zout[i0] = zw[i0] + 0.5f * (k1in[i0] + t0);
        zout[i1] = zw[i1] + 0.5f * (k1in[i1] + t1);
    }
}

// ----- decoder: nearest x2 (XY) + conv 64->18 3x3x3 + fast_logits[3] -------
__global__ void __launch_bounds__(144) k_dec(const float* __restrict__ zf,
                                             const float4* __restrict__ wq,
                                             const float* __restrict__ b,
                                             const float* __restrict__ flast,
                                             float* __restrict__ out) {
    extern __shared__ __align__(16) float patch[];
    int tid = threadIdx.x;
    int gx = blockIdx.x / 100, gy = blockIdx.x - gx * 100;
    int x0 = gx * 4, y0 = gy * 2;
    int dx0 = x0 / 2 - 1, dy0 = y0 / 2 - 1;
    for (int u = tid; u < 768; u += 144) {
        int ci = u / 12; int r = u - ci * 12; int dx = r / 3; int dy = r - dx * 3;
        int ddx = dx0 + dx, ddy = dy0 + dy;
        float* col = patch + u * 20;
        if ((unsigned)ddx < (unsigned)Xd && (unsigned)ddy < (unsigned)Yd) {
            const float4* g = (const float4*)(zf + (size_t)ci * NV + (ddx * Yd + ddy) * Zd);
            float4 a0 = g[0], a1 = g[1], a2 = g[2], a3 = g[3];
            col[0] = 0.f;
            col[1] = a0.x; col[2] = a0.y; col[3] = a0.z; col[4] = a0.w;
            col[5] = a1.x; col[6] = a1.y; col[7] = a1.z; col[8] = a1.w;
            col[9] = a2.x; col[10] = a2.y; col[11] = a2.z; col[12] = a2.w;
            col[13] = a3.x; col[14] = a3.y; col[15] = a3.z; col[16] = a3.w;
            col[17] = 0.f;
        } else {
            float4 zz = make_float4(0.f, 0.f, 0.f, 0.f);
            float4* c4 = (float4*)col;
            c4[0] = zz; c4[1] = zz; c4[2] = zz; c4[3] = zz; c4[4] = zz;
        }
    }
    __syncthreads();
    int colid = tid / 18, co = tid - colid * 18;
    int lx = colid >> 1, ly = colid & 1;
    int x = x0 + lx, y = y0 + ly;
    int par = (lx & 1) * 2 + ly;
    int ux = ((x - 1) >> 1) - dx0;
    int vy = ((y - 1) >> 1) - dy0;
    float bb = __ldg(&b[co]);
    uint64_t acc[8];
    uint64_t binit = dup2(bb);
#pragma unroll
    for (int i = 0; i < 8; i++) acc[i] = binit;
#pragma unroll 1
    for (int ci = 0; ci < 64; ci++) {
#pragma unroll
        for (int tap = 0; tap < 4; tap++) {
            int du = tap >> 1, dv = tap & 1;
            const float* col = patch + (ci * 12 + (ux + du) * 3 + (vy + dv)) * 20;
            const ulonglong2* v2 = (const ulonglong2*)col;
            uint64_t pe[9];
            ulonglong2 t0 = v2[0], t1 = v2[1], t2 = v2[2], t3 = v2[3];
            pe[0] = t0.x; pe[1] = t0.y; pe[2] = t1.x; pe[3] = t1.y;
            pe[4] = t2.x; pe[5] = t2.y; pe[6] = t3.x; pe[7] = t3.y;
            pe[8] = ((const uint64_t*)col)[8];
            float4 w = __ldg(&wq[((par * 64 + ci) * 4 + tap) * 18 + co]);
            uint64_t w0 = dup2(w.x), w1 = dup2(w.y), w2 = dup2(w.z);
#pragma unroll
            for (int i = 0; i < 8; i++) ffma2(acc[i], pe[i], w0);
#pragma unroll
            for (int i = 0; i < 8; i++) {
                uint64_t sh = pack2(hi2(pe[i]), lo2(pe[i + 1]));
                ffma2(acc[i], sh, w1);
            }
#pragma unroll
            for (int i = 0; i < 8; i++) ffma2(acc[i], pe[i + 1], w2);
        }
    }
    int ob = co * NVF + (x * Y + y) * Z;
#pragma unroll
    for (int q = 0; q < 4; q++) {
        float2 u0 = unpack2(acc[2 * q]);
        float2 u1 = unpack2(acc[2 * q + 1]);
        out[ob + 4 * q + 0] = u0.x + __ldg(&flast[ob + 4 * q + 0]);
        out[ob + 4 * q + 1] = u0.y + __ldg(&flast[ob + 4 * q + 1]);
        out[ob + 4 * q + 2] = u1.x + __ldg(&flast[ob + 4 * q + 2]);
        out[ob + 4 * q + 3] = u1.y + __ldg(&flast[ob + 4 * q + 3]);
    }
}

// --------------------------------- host ------------------------------------
static void* sym_addr(const void* s) { void* p = nullptr; cudaGetSymbolAddress(&p, s); return p; }

extern "C" void kernel_launch(void* const* d_in, const int* in_sizes, int n_in,
                              void* d_out, int out_size) {
    (void)in_sizes; (void)n_in; (void)out_size;
    const float* fast_logits = (const float*)d_in[0];
    const float* slow_logits = (const float*)d_in[1];
    const float* pose   = (const float*)d_in[2];
    const float* fe_w   = (const float*)d_in[3];
    const float* fe_b   = (const float*)d_in[4];
    const float* se_w   = (const float*)d_in[5];
    const float* se_b   = (const float*)d_in[6];
    const float* ctrl_w = (const float*)d_in[7];
    const float* ctrl_b = (const float*)d_in[8];
    const float* gin_w  = (const float*)d_in[9];
    const float* gin_b  = (const float*)d_in[10];
    const float* gbw    = (const float*)d_in[11];
    const float* gbb    = (const float*)d_in[12];
    const float* gns    = (const float*)d_in[13];
    const float* gnb    = (const float*)d_in[14];
    const float* gout_w = (const float*)d_in[15];
    const float* gout_b = (const float*)d_in[16];
    const float* dec_w  = (const float*)d_in[17];
    const float* dec_b  = (const float*)d_in[18];
    const int*   ts     = (const int*)d_in[19];
    float* out = (float*)d_out;

    float*  p_fast  = (float*)sym_addr(d_fast);
    float*  p_z     = (float*)sym_addr(d_z);
    float*  p_zw    = (float*)sym_addr(d_zw);
    float*  p_fadv  = (float*)sym_addr(d_fadv);
    float*  p_dX    = (float*)sym_addr(d_dX);
    float*  p_k1    = (float*)sym_addr(d_k1);
    float*  p_h     = (float*)sym_addr(d_h);
    float*  p_h2    = (float*)sym_addr(d_h2);
    float*  p_c     = (float*)sym_addr(d_c);
    float*  p_c2    = (float*)sym_addr(d_c2);
    float4* p_wfe4  = (float4*)sym_addr(d_wfe4);
    float4* p_wse4  = (float4*)sym_addr(d_wse4);
    float4* p_wbA   = (float4*)sym_addr(d_wbA);
    float2* p_wbB   = (float2*)sym_addr(d_wbB);
    float4* p_wdecv = (float4*)sym_addr(d_wdecv);
    float*  p_wctrl = (float*)sym_addr(d_wctrl);
    float*  p_wgin  = (float*)sym_addr(d_wgin);
    float*  p_wgout = (float*)sym_addr(d_wgout);

    const int SM1 = 3 * 8 * 10 * 20 * 4;   // 19200
    const int SM2 = 3 * 8 * 12 * 20 * 4;   // 23040
    const int SM3 = 3 * 8 * 14 * 24 * 4;   // 32256
    const int SMD = 768 * 20 * 4;          // 61440
    cudaFuncSetAttribute(k_body<1>, cudaFuncAttributeMaxDynamicSharedMemorySize, SM1);
    cudaFuncSetAttribute(k_body<2>, cudaFuncAttributeMaxDynamicSharedMemorySize, SM2);
    cudaFuncSetAttribute(k_body<3>, cudaFuncAttributeMaxDynamicSharedMemorySize, SM3);
    cudaFuncSetAttribute(k_dec, cudaFuncAttributeMaxDynamicSharedMemorySize, SMD);

    k_prep<<<248, 256>>>(fe_w, se_w, gbw, dec_w, ctrl_w, gin_w, gout_w);     // 0
    k_transforms<<<1, 1>>>(pose, ts);                                        // 1
    k_enc<<<dim3(NCOLS / 2, 4), 128>>>(fast_logits, p_wfe4, fe_b, p_fast, nullptr);  // 2
    k_enc<<<dim3(NCOLS / 2, 1), 128>>>(slow_logits, p_wse4, se_b, p_z, p_fast);      // 3 (profiled)

    for (int k = 0; k < 3; k++) {
        const float* fk  = p_fast + (size_t)k * 64 * NV;
        const float* fk1 = p_fast + (size_t)(k + 1) * 64 * NV;
        k_warpctrl<<<NV / 256, 256>>>(p_z, fk, fk1, p_wctrl, ctrl_b,
                                      p_zw, p_fadv, p_dX, k);
        int inst0 = k * 6;
        // ---- pass 0 ----
        k_gin<<<NV / 256, 128>>>(p_zw, nullptr, p_fadv, p_wgin, gin_b, p_h);
        k_body<1><<<1300, 128, SM1>>>(p_h, nullptr, nullptr, nullptr, nullptr, 0,
                                      p_wbA, p_wbB, gbb, p_c, inst0);
        k_body<2><<<1300, 128, SM2>>>(p_h, p_c, p_h2, gns, gnb, inst0,
                                      p_wbA + 4608, p_wbB + 4608, gbb + 32, p_c2, inst0 + 1);
        k_body<3><<<1300, 128, SM3>>>(p_h2, p_c2, p_h, gns + 32, gnb + 32, inst0 + 1,
                                      p_wbA + 2 * 4608, p_wbB + 2 * 4608, gbb + 64, p_c, inst0 + 2);
        // fused: gout(pass0) -> k1 ; gin(pass1) -> h
        k_goutgin<<<NV / 256, 256>>>(p_h, p_wgout, gout_b, p_dX,
                                     p_c, gns + 64, gnb + 64, inst0 + 2,
                                     p_zw, fk1, p_wgin, gin_b, p_k1, p_h);
        // ---- pass 1 ----
        int inst1 = inst0 + 3;
        k_body<1><<<1300, 128, SM1>>>(p_h, nullptr, nullptr, nullptr, nullptr, 0,
                                      p_wbA, p_wbB, gbb, p_c, inst1);
        k_body<2><<<1300, 128, SM2>>>(p_h, p_c, p_h2, gns, gnb, inst1,
                                      p_wbA + 4608, p_wbB + 4608, gbb + 32, p_c2, inst1 + 1);
        k_body<3><<<1300, 128, SM3>>>(p_h2, p_c2, p_h, gns + 32, gnb + 32, inst1 + 1,
                                      p_wbA + 2 * 4608, p_wbB + 2 * 4608, gbb + 64, p_c, inst1 + 2);
        k_gout<<<NV / 256, 256>>>(p_h, p_wgout, gout_b, p_dX,
                                  p_c, gns + 64, gnb + 64, inst1 + 2,
                                  p_zw, p_k1, p_z);
    }
    k_dec<<<5000, 144, SMD>>>(p_z, p_wdecv, dec_b, fast_logits + (size_t)3 * CL * NVF, out);
}

// round 17
// speedup vs baseline: 1.0059x; 1.0059x over previous
#include <cuda_runtime.h>
#include <math.h>
#include <stdint.h>

namespace {
constexpr int CL = 18, X = 200, Y = 200, Z = 16;
constexpr int Xd = 100, Yd = 100, Zd = 16;
constexpr int NV = Xd * Yd * Zd;      // 160000
constexpr int NCOLS = Xd * Yd;        // 10000
constexpr int NVF = X * Y * Z;        // 640000
}

// ---------------- packed fp32x2 helpers ------------------------------------
__device__ __forceinline__ uint64_t pack2(float a, float b) {
    uint64_t r; asm("mov.b64 %0, {%1, %2};" : "=l"(r) : "f"(a), "f"(b)); return r;
}
__device__ __forceinline__ uint64_t dup2(float a) {
    uint64_t r; asm("mov.b64 %0, {%1, %1};" : "=l"(r) : "f"(a)); return r;
}
__device__ __forceinline__ void ffma2(uint64_t& d, uint64_t a, uint64_t b) {
    asm("fma.rn.f32x2 %0, %1, %2, %0;" : "+l"(d) : "l"(a), "l"(b));
}
__device__ __forceinline__ float2 unpack2(uint64_t v) {
    float2 r; asm("mov.b64 {%0, %1}, %2;" : "=f"(r.x), "=f"(r.y) : "l"(v)); return r;
}
__device__ __forceinline__ float lo2(uint64_t v) {
    float a, b; asm("mov.b64 {%0, %1}, %2;" : "=f"(a), "=f"(b) : "l"(v)); return a;
}
__device__ __forceinline__ float hi2(uint64_t v) {
    float a, b; asm("mov.b64 {%0, %1}, %2;" : "=f"(a), "=f"(b) : "l"(v)); return b;
}
__device__ __forceinline__ void ffma_lo(uint64_t& d, float a, float b) {
    asm("{\n\t.reg .f32 lo, hi;\n\tmov.b64 {lo, hi}, %0;\n\t"
        "fma.rn.f32 lo, %1, %2, lo;\n\tmov.b64 %0, {lo, hi};\n\t}"
        : "+l"(d) : "f"(a), "f"(b));
}
__device__ __forceinline__ void ffma_hi(uint64_t& d, float a, float b) {
    asm("{\n\t.reg .f32 lo, hi;\n\tmov.b64 {lo, hi}, %0;\n\t"
        "fma.rn.f32 hi, %1, %2, hi;\n\tmov.b64 %0, {lo, hi};\n\t}"
        : "+l"(d) : "f"(a), "f"(b));
}
__device__ __forceinline__ float tanh_ap(float x) {
    float y; asm("tanh.approx.f32 %0, %1;" : "=f"(y) : "f"(x)); return y;
}

// ------------------------- device-global scratch ---------------------------
__device__ float d_fast[4 * 64 * NV];
__device__ float d_z[64 * NV];
__device__ float d_zw[64 * NV];
__device__ float d_dX[64 * NV];
__device__ float d_k1[64 * NV];
__device__ float d_h[32 * NV];
__device__ float d_h2[32 * NV];
__device__ float d_c[32 * NV];
__device__ float d_c2[32 * NV];
__device__ float d_tinv[3][12];
__device__ float d_dtau[3];
__device__ float d_gsum[19 * 8];
__device__ float d_gss[19 * 8];
__device__ float4 d_wfe4[18 * 9 * 64];
__device__ float4 d_wse4[18 * 9 * 64];
__device__ float4 d_wbA[3][288 * 16];
__device__ float2 d_wbB[3][288 * 16];
__device__ float4 d_wdecv[4 * 64 * 4 * 18];
__device__ float d_wctrl[65 * 64];
__device__ float d_wgin[128 * 32];
__device__ float d_wgout[32 * 64];

// ---- one fused prep kernel: repacks + GN reset + pose transforms ----------
__global__ void k_prep(const float* __restrict__ fe, const float* __restrict__ se,
                       const float* __restrict__ gb, const float* __restrict__ dec,
                       const float* __restrict__ ctrl, const float* __restrict__ gin,
                       const float* __restrict__ gout,
                       const float* __restrict__ pose, const int* __restrict__ ts) {
    // pose transforms: one thread of the last block
    if (blockIdx.x == gridDim.x - 1 && threadIdx.x == 255) {
        for (int k = 0; k < 3; k++) {
            float A[4][4], Iv[4][4];
            for (int r = 0; r < 4; r++)
                for (int c = 0; c < 4; c++) {
                    A[r][c] = pose[k * 16 + r * 4 + c];
                    Iv[r][c] = (r == c) ? 1.f : 0.f;
                }
            for (int c = 0; c < 4; c++) {
                int piv = c;
                for (int r = c + 1; r < 4; r++)
                    if (fabsf(A[r][c]) > fabsf(A[piv][c])) piv = r;
                if (piv != c)
                    for (int j = 0; j < 4; j++) {
                        float t = A[c][j]; A[c][j] = A[piv][j]; A[piv][j] = t;
                        t = Iv[c][j]; Iv[c][j] = Iv[piv][j]; Iv[piv][j] = t;
                    }
                float dinv = 1.f / A[c][c];
                for (int j = 0; j < 4; j++) { A[c][j] *= dinv; Iv[c][j] *= dinv; }
                for (int r = 0; r < 4; r++) {
                    if (r == c) continue;
                    float f = A[r][c];
                    for (int j = 0; j < 4; j++) { A[r][j] -= f * A[c][j]; Iv[r][j] -= f * Iv[c][j]; }
                }
            }
            const float* B = pose + (k + 1) * 16;
            for (int r = 0; r < 3; r++)
                for (int c = 0; c < 4; c++) {
                    float s = 0.f;
                    for (int j = 0; j < 4; j++) s += Iv[r][j] * B[j * 4 + c];
                    d_tinv[k][r * 4 + c] = s;
                }
            d_dtau[k] = (float)(ts[k + 1] - ts[k]) * 1e-6f;
        }
    }
    int i = blockIdx.x * 256 + threadIdx.x;
    if (i < 152) { d_gsum[i] = 0.f; d_gss[i] = 0.f; }
    if (i < 10368) {
        int ci = i / 576; int r = i - ci * 576; int dd = r >> 6; int co = r & 63;
        const float* s = fe + co * 486 + ci * 27 + dd * 3;
        d_wfe4[i] = make_float4(s[0], s[1], s[2], 0.f); return;
    }
    i -= 10368;
    if (i < 10368) {
        int ci = i / 576; int r = i - ci * 576; int dd = r >> 6; int co = r & 63;
        const float* s = se + co * 486 + ci * 27 + dd * 3;
        d_wse4[i] = make_float4(s[0], s[1], s[2], 0.f); return;
    }
    i -= 10368;
    if (i < 3 * 4608) {
        int lay = i / 4608; int u = i - lay * 4608;
        int t = u >> 4, p = u & 15;
        int ci = t / 9, tap = t - ci * 9;
        const float* g0 = gb + lay * 27648 + (2 * p) * 864 + ci * 27 + tap * 3;
        const float* g1 = g0 + 864;
        d_wbA[lay][u] = make_float4(g0[0], g1[0], g0[1], g1[1]);
        d_wbB[lay][u] = make_float2(g0[2], g1[2]);
        return;
    }
    i -= 3 * 4608;
    if (i < 18432) {
        int par = i / 4608; int r = i - par * 4608;
        int ci = r / 72; int r2 = r - ci * 72;
        int tap = r2 / 18; int co = r2 - tap * 18;
        int du = tap >> 1, dv = tap & 1;
        int px = par >> 1, py = par & 1;
        float s0 = 0.f, s1 = 0.f, s2 = 0.f;
        for (int kx = 0; kx < 3; kx++) {
            bool okx = (px == 0) ? (du == 0 ? (kx == 0) : (kx >= 1))
                                 : (du == 0 ? (kx <= 1) : (kx == 2));
            if (!okx) continue;
            for (int ky = 0; ky < 3; ky++) {
                bool oky = (py == 0) ? (dv == 0 ? (ky == 0) : (ky >= 1))
                                     : (dv == 0 ? (ky <= 1) : (ky == 2));
                if (!oky) continue;
                const float* s = dec + (((co * 64 + ci) * 3 + kx) * 3 + ky) * 3;
                s0 += s[0]; s1 += s[1]; s2 += s[2];
            }
        }
        d_wdecv[i] = make_float4(s0, s1, s2, 0.f);
        return;
    }
    i -= 18432;
    if (i < 4160) { int j = i >> 6, co = i & 63; d_wctrl[j * 64 + co] = ctrl[co * 65 + j]; return; }
    i -= 4160;
    if (i < 4096) { int j = i >> 5, co = i & 31; d_wgin[j * 32 + co] = gin[co * 128 + j]; return; }
    i -= 4096;
    if (i < 2048) { int j = i >> 6, co = i & 63; d_wgout[j * 64 + co] = gout[co * 32 + j]; return; }
}

// -------- encoder conv 18->64, 3x3x3, stride (2,2,1), pad 1, ReLU ----------
__global__ void __launch_bounds__(128) k_enc(const float* __restrict__ inbase,
                                             const float4* __restrict__ wq,
                                             const float* __restrict__ b,
                                             float* __restrict__ outbase,
                                             const float* __restrict__ subsrc) {
    __shared__ __align__(16) float patch[2 * 162 * 24];
    const float* in = inbase + (size_t)blockIdx.y * CL * NVF;
    float* out = outbase + (size_t)blockIdx.y * 64 * NV;
    int tid = threadIdx.x;
    int p0 = blockIdx.x * 2;
    for (int u = tid; u < 324; u += 128) {
        int lc = u / 162; int r = u - lc * 162; int ci = r / 9; int dd = r - ci * 9;
        int p = p0 + lc; int x = p / Yd, y = p - x * Yd;
        int ix = 2 * x - 1 + dd / 3, iy = 2 * y - 1 + dd % 3;
        float* col = patch + u * 24;
        if ((unsigned)ix < (unsigned)X && (unsigned)iy < (unsigned)Y) {
            const float4* g = (const float4*)(in + ((size_t)(ci * X + ix) * Y + iy) * Z);
            float4 a0 = g[0], a1 = g[1], a2 = g[2], a3 = g[3];
            col[0] = 0.f;
            col[1] = a0.x; col[2] = a0.y; col[3] = a0.z; col[4] = a0.w;
            col[5] = a1.x; col[6] = a1.y; col[7] = a1.z; col[8] = a1.w;
            col[9] = a2.x; col[10] = a2.y; col[11] = a2.z; col[12] = a2.w;
            col[13] = a3.x; col[14] = a3.y; col[15] = a3.z; col[16] = a3.w;
            col[17] = 0.f;
        } else {
            float4 zz = make_float4(0.f, 0.f, 0.f, 0.f);
            float4* c4 = (float4*)col;
            c4[0] = zz; c4[1] = zz; c4[2] = zz; c4[3] = zz;
            col[16] = 0.f; col[17] = 0.f;
        }
    }
    __syncthreads();
    int lc = tid >> 6, c = tid & 63;
    float bb = __ldg(&b[c]);
    uint64_t acc[8];
    uint64_t binit = dup2(bb);
#pragma unroll
    for (int i = 0; i < 8; i++) acc[i] = binit;
    const float* pb = patch + lc * 162 * 24;
#pragma unroll 1
    for (int ci = 0; ci < 18; ci++) {
#pragma unroll
        for (int dd = 0; dd < 9; dd++) {
            const float* col = pb + (ci * 9 + dd) * 24;
            const ulonglong2* v2 = (const ulonglong2*)col;
            uint64_t pe[9];
            ulonglong2 t0 = v2[0], t1 = v2[1], t2 = v2[2], t3 = v2[3];
            pe[0] = t0.x; pe[1] = t0.y; pe[2] = t1.x; pe[3] = t1.y;
            pe[4] = t2.x; pe[5] = t2.y; pe[6] = t3.x; pe[7] = t3.y;
            pe[8] = ((const uint64_t*)col)[8];
            float4 w = __ldg(&wq[(ci * 9 + dd) * 64 + c]);
            uint64_t w0 = dup2(w.x), w2 = dup2(w.z);
#pragma unroll
            for (int i = 0; i < 8; i++) ffma2(acc[i], pe[i], w0);
#pragma unroll
            for (int i = 0; i < 8; i++) {
                ffma_lo(acc[i], hi2(pe[i]), w.y);
                ffma_hi(acc[i], lo2(pe[i + 1]), w.y);
            }
#pragma unroll
            for (int i = 0; i < 8; i++) ffma2(acc[i], pe[i + 1], w2);
        }
    }
    size_t obase = (size_t)c * NV + (size_t)(p0 + lc) * 16;
    float* op = out + obase;
    float4* o4 = (float4*)op;
    if (subsrc) {
        const float4* s4 = (const float4*)(subsrc + obase);
#pragma unroll
        for (int q = 0; q < 4; q++) {
            float2 u0 = unpack2(acc[2 * q]);
            float2 u1 = unpack2(acc[2 * q + 1]);
            float4 sv = s4[q];
            o4[q] = make_float4(fmaxf(u0.x, 0.f) - sv.x, fmaxf(u0.y, 0.f) - sv.y,
                                fmaxf(u1.x, 0.f) - sv.z, fmaxf(u1.y, 0.f) - sv.w);
        }
    } else {
#pragma unroll
        for (int q = 0; q < 4; q++) {
            float2 u0 = unpack2(acc[2 * q]);
            float2 u1 = unpack2(acc[2 * q + 1]);
            o4[q] = make_float4(fmaxf(u0.x, 0.f), fmaxf(u0.y, 0.f), fmaxf(u1.x, 0.f), fmaxf(u1.y, 0.f));
        }
    }
}

// ---- fused warp + ctrl + gin(pass0): one pass over 64 channels ------------
//   zw_c, fadv_c by trilinear warp (fadv never hits gmem)
//   dX = Wctrl [ft - fadv; dtau] + b
//   h  = relu(Wgin [zw; fadv] + bg)
__global__ void __launch_bounds__(128) k_wcg(const float* __restrict__ zin,
                                             const float* __restrict__ fin,
                                             const float* __restrict__ ft,
                                             const float* __restrict__ wt,
                                             const float* __restrict__ b,
                                             const float* __restrict__ wg,
                                             const float* __restrict__ bg,
                                             float* __restrict__ zw,
                                             float* __restrict__ dX,
                                             float* __restrict__ h, int step) {
    __shared__ __align__(16) float w[65 * 64 + 64 + 128 * 32 + 32];
    int tid = threadIdx.x;
    for (int i = tid; i < 65 * 64; i += 128) w[i] = wt[i];
    if (tid < 64) w[65 * 64 + tid] = b[tid];
    float* wgs = w + 65 * 64 + 64;
    for (int i = tid; i < 128 * 32; i += 128) wgs[i] = wg[i];
    if (tid < 32) wgs[128 * 32 + tid] = bg[tid];
    __syncthreads();
    const uint64_t* w64 = (const uint64_t*)w;
    const uint64_t* b64 = (const uint64_t*)(w + 65 * 64);
    const uint64_t* wg64 = (const uint64_t*)wgs;
    const uint64_t* bg64 = (const uint64_t*)(wgs + 128 * 32);
    int v = blockIdx.x * 128 + tid;
    int p = v >> 4, z = v & 15;
    int x = p / Yd, y = p - x * Yd;
    float wxw = -40.f + (x + 0.5f) * 0.8f;
    float wyw = -40.f + (y + 0.5f) * 0.8f;
    float wzw = -1.f + (z + 0.5f) * 0.4f;
    const float* M = d_tinv[step];
    float px = M[0] * wxw + M[1] * wyw + M[2] * wzw + M[3];
    float py = M[4] * wxw + M[5] * wyw + M[6] * wzw + M[7];
    float pz = M[8] * wxw + M[9] * wyw + M[10] * wzw + M[11];
    float gxf = (px + 40.f) / 0.8f - 0.5f;
    float gyf = (py + 40.f) / 0.8f - 0.5f;
    float gzf = (pz + 1.f) / 0.4f - 0.5f;
    gxf = fminf(fmaxf(gxf, 0.f), 99.f);
    gyf = fminf(fmaxf(gyf, 0.f), 99.f);
    gzf = fminf(fmaxf(gzf, 0.f), 15.f);
    float fx0 = floorf(gxf), fy0 = floorf(gyf), fz0 = floorf(gzf);
    int x0 = (int)fx0, y0 = (int)fy0, z0 = (int)fz0;
    int x1 = min(x0 + 1, 99), y1 = min(y0 + 1, 99), z1 = min(z0 + 1, 15);
    float fx = gxf - fx0, fy = gyf - fy0, fz = gzf - fz0;
    float cx0 = 1.f - fx, cy0 = 1.f - fy, cz0 = 1.f - fz;
    float w000 = cx0 * cy0 * cz0, w100 = fx * cy0 * cz0, w010 = cx0 * fy * cz0, w110 = fx * fy * cz0;
    float w001 = cx0 * cy0 * fz, w101 = fx * cy0 * fz, w011 = cx0 * fy * fz, w111 = fx * fy * fz;
    int o00 = (x0 * Yd + y0) * Zd, o01 = (x0 * Yd + y1) * Zd;
    int o10 = (x1 * Yd + y0) * Zd, o11 = (x1 * Yd + y1) * Zd;
    uint64_t acc[32];
#pragma unroll
    for (int j = 0; j < 32; j++) acc[j] = b64[j];
    uint64_t gacc[16];
#pragma unroll
    for (int j = 0; j < 16; j++) gacc[j] = bg64[j];
#pragma unroll 1
    for (int c = 0; c < 64; c++) {
        const float* a = zin + c * NV;
        float r = __ldg(a + o00 + z0) * w000 + __ldg(a + o10 + z0) * w100
                + __ldg(a + o01 + z0) * w010 + __ldg(a + o11 + z0) * w110
                + __ldg(a + o00 + z1) * w001 + __ldg(a + o10 + z1) * w101
                + __ldg(a + o01 + z1) * w011 + __ldg(a + o11 + z1) * w111;
        zw[c * NV + v] = r;
        const float* f = fin + c * NV;
        float r2 = __ldg(f + o00 + z0) * w000 + __ldg(f + o10 + z0) * w100
                 + __ldg(f + o01 + z0) * w010 + __ldg(f + o11 + z0) * w110
                 + __ldg(f + o00 + z1) * w001 + __ldg(f + o10 + z1) * w101
                 + __ldg(f + o01 + z1) * w011 + __ldg(f + o11 + z1) * w111;
        float val = __ldg(&ft[c * NV + v]) - r2;
        uint64_t vd = dup2(val);
#pragma unroll
        for (int j = 0; j < 32; j++) ffma2(acc[j], w64[c * 32 + j], vd);
        uint64_t vda = dup2(r), vdb = dup2(r2);
#pragma unroll
        for (int j = 0; j < 16; j++) {
            ffma2(gacc[j], wg64[c * 16 + j], vda);
            ffma2(gacc[j], wg64[(64 + c) * 16 + j], vdb);
        }
    }
    {
        uint64_t vd = dup2(d_dtau[step]);
#pragma unroll
        for (int j = 0; j < 32; j++) ffma2(acc[j], w64[64 * 32 + j], vd);
    }
#pragma unroll
    for (int j = 0; j < 32; j++) {
        float2 u = unpack2(acc[j]);
        dX[(2 * j) * NV + v] = u.x;
        dX[(2 * j + 1) * NV + v] = u.y;
    }
#pragma unroll
    for (int j = 0; j < 16; j++) {
        float2 u = unpack2(gacc[j]);
        h[(2 * j) * NV + v] = fmaxf(u.x, 0.f);
        h[(2 * j + 1) * NV + v] = fmaxf(u.y, 0.f);
    }
}

// ------- dilated body conv 32->32, 3x3x3, dil D ----------------------------
template <int D>
__global__ void __launch_bounds__(128, 7) k_body(const float* __restrict__ hin,
                                                 const float* __restrict__ gnc,
                                                 float* __restrict__ hwb,
                                                 const float* __restrict__ gsc,
                                                 const float* __restrict__ gbi,
                                                 int gn_inst,
                                                 const float4* __restrict__ wA,
                                                 const float2* __restrict__ wB,
                                                 const float* __restrict__ b,
                                                 float* __restrict__ cout, int inst) {
    extern __shared__ __align__(16) float patch[];
    constexpr int STRIDE = (D == 3) ? 24 : 20;
    constexpr int SY = 8 + 2 * D;
    constexpr int NU = 3 * 8 * SY;
    __shared__ float gsh[8], gqh[8];
    int tid = threadIdx.x;
    if (tid < 8) { gsh[tid] = 0.f; gqh[tid] = 0.f; }
    int bx = blockIdx.x;
    int x = bx / 13; int ty = bx - x * 13; int y0 = ty * 8;
    int w = tid >> 5, l = tid & 31;
    int hh = l >> 4, p = l & 15;
    int cyl = 2 * w + hh;
    int colY = y0 + cyl;
    bool act = (y0 + 2 * w < 100);
    int coA = 2 * p, coB = coA + 1;
    uint64_t accA[8], accB[8];
    uint64_t bia = dup2(__ldg(&b[coA])), bib = dup2(__ldg(&b[coB]));
#pragma unroll
    for (int i = 0; i < 8; i++) { accA[i] = bia; accB[i] = bib; }
    constexpr int NPE = 8 + D;
    const float ginv = 1.f / (4.f * (float)NV);
#pragma unroll 1
    for (int s = 0; s < 4; s++) {
        for (int u = tid; u < NU; u += 128) {
            int kx = u / (8 * SY); int r = u - kx * (8 * SY);
            int cis = r / SY; int iyi = r - cis * SY;
            int ci = 8 * s + cis;
            int ix = x + (kx - 1) * D, iy = y0 - D + iyi;
            float* col = patch + u * STRIDE;
            if ((unsigned)ix < (unsigned)Xd && (unsigned)iy < (unsigned)Yd) {
                size_t off = (size_t)ci * NV + (ix * Yd + iy) * Zd;
                const float4* g = (const float4*)(hin + off);
                float4 a0 = g[0], a1 = g[1], a2 = g[2], a3 = g[3];
                if (gnc) {
                    int gg = ci >> 2;
                    float m = d_gsum[gn_inst * 8 + gg] * ginv;
                    float var = d_gss[gn_inst * 8 + gg] * ginv - m * m;
                    float rr = rsqrtf(var + 1e-5f);
                    float sc = __ldg(&gsc[ci]) * rr;
                    float bi = __ldg(&gbi[ci]) - m * sc;
                    const float4* gc = (const float4*)(gnc + off);
                    float4 c0 = gc[0], c1 = gc[1], c2 = gc[2], c3 = gc[3];
                    a0.x += fmaxf(c0.x * sc + bi, 0.f); a0.y += fmaxf(c0.y * sc + bi, 0.f);
                    a0.z += fmaxf(c0.z * sc + bi, 0.f); a0.w += fmaxf(c0.w * sc + bi, 0.f);
                    a1.x += fmaxf(c1.x * sc + bi, 0.f); a1.y += fmaxf(c1.y * sc + bi, 0.f);
                    a1.z += fmaxf(c1.z * sc + bi, 0.f); a1.w += fmaxf(c1.w * sc + bi, 0.f);
                    a2.x += fmaxf(c2.x * sc + bi, 0.f); a2.y += fmaxf(c2.y * sc + bi, 0.f);
                    a2.z += fmaxf(c2.z * sc + bi, 0.f); a2.w += fmaxf(c2.w * sc + bi, 0.f);
                    a3.x += fmaxf(c3.x * sc + bi, 0.f); a3.y += fmaxf(c3.y * sc + bi, 0.f);
                    a3.z += fmaxf(c3.z * sc + bi, 0.f); a3.w += fmaxf(c3.w * sc + bi, 0.f);
                    float4* hw = (float4*)(hwb + off);
                    hw[0] = a0; hw[1] = a1; hw[2] = a2; hw[3] = a3;
                }
#pragma unroll
                for (int j = 0; j < D; j++) col[j] = 0.f;
                col[D + 0] = a0.x; col[D + 1] = a0.y; col[D + 2] = a0.z; col[D + 3] = a0.w;
                col[D + 4] = a1.x; col[D + 5] = a1.y; col[D + 6] = a1.z; col[D + 7] = a1.w;
                col[D + 8] = a2.x; col[D + 9] = a2.y; col[D + 10] = a2.z; col[D + 11] = a2.w;
                col[D + 12] = a3.x; col[D + 13] = a3.y; col[D + 14] = a3.z; col[D + 15] = a3.w;
#pragma unroll
                for (int j = D + 16; j < 16 + 2 * D; j++) col[j] = 0.f;
            } else {
                float4 zz = make_float4(0.f, 0.f, 0.f, 0.f);
                float4* c4 = (float4*)col;
#pragma unroll
                for (int j = 0; j < STRIDE / 4; j++) c4[j] = zz;
            }
        }
        __syncthreads();
        if (act) {
#pragma unroll 1
            for (int cis = 0; cis < 8; cis++) {
#pragma unroll
                for (int kx = 0; kx < 3; kx++) {
#pragma unroll
                    for (int ky = 0; ky < 3; ky++) {
                        const float* col = patch + (((kx * 8 + cis) * SY) + cyl + ky * D) * STRIDE;
                        uint64_t pe[11];
                        const ulonglong2* v2 = (const ulonglong2*)col;
#pragma unroll
                        for (int q = 0; q < NPE / 2; q++) {
                            ulonglong2 t = v2[q];
                            pe[2 * q] = t.x; pe[2 * q + 1] = t.y;
                        }
                        if constexpr (NPE & 1) pe[NPE - 1] = ((const uint64_t*)col)[NPE - 1];
                        int widx = ((8 * s + cis) * 9 + kx * 3 + ky) * 16 + p;
                        float4 wa = __ldg(&wA[widx]);
                        float2 wb = __ldg(&wB[widx]);
                        uint64_t w0a = dup2(wa.x), w0b = dup2(wa.y);
                        uint64_t w2a = dup2(wb.x), w2b = dup2(wb.y);
#pragma unroll
                        for (int i = 0; i < 8; i++) { ffma2(accA[i], pe[i], w0a); ffma2(accB[i], pe[i], w0b); }
                        if constexpr ((D & 1) == 0) {
                            uint64_t w1a = dup2(wa.z), w1b = dup2(wa.w);
#pragma unroll
                            for (int i = 0; i < 8; i++) {
                                ffma2(accA[i], pe[i + D / 2], w1a);
                                ffma2(accB[i], pe[i + D / 2], w1b);
                            }
                        } else {
                            uint64_t w1a = dup2(wa.z), w1b = dup2(wa.w);
#pragma unroll
                            for (int i = 0; i < 8; i++) {
                                uint64_t sh = pack2(hi2(pe[i + (D - 1) / 2]), lo2(pe[i + (D + 1) / 2]));
                                ffma2(accA[i], sh, w1a);
                                ffma2(accB[i], sh, w1b);
                            }
                        }
#pragma unroll
                        for (int i = 0; i < 8; i++) { ffma2(accA[i], pe[i + D], w2a); ffma2(accB[i], pe[i + D], w2b); }
                    }
                }
            }
        }
        __syncthreads();
    }
    if (act) {
        float s = 0.f, ss = 0.f;
        size_t cb = (size_t)(x * Yd + colY) * 16;
        float4* oA = (float4*)(cout + (size_t)coA * NV + cb);
        float4* oB = (float4*)(cout + (size_t)coB * NV + cb);
#pragma unroll
        for (int q = 0; q < 4; q++) {
            float2 a0 = unpack2(accA[2 * q]);
            float2 a1 = unpack2(accA[2 * q + 1]);
            s += a0.x + a0.y + a1.x + a1.y;
            ss += a0.x * a0.x + a0.y * a0.y + a1.x * a1.x + a1.y * a1.y;
            oA[q] = make_float4(a0.x, a0.y, a1.x, a1.y);
            float2 b0 = unpack2(accB[2 * q]);
            float2 b1 = unpack2(accB[2 * q + 1]);
            s += b0.x + b0.y + b1.x + b1.y;
            ss += b0.x * b0.x + b0.y * b0.y + b1.x * b1.x + b1.y * b1.y;
            oB[q] = make_float4(b0.x, b0.y, b1.x, b1.y);
        }
        atomicAdd(&gsh[p >> 1], s);
        atomicAdd(&gqh[p >> 1], ss);
    }
    __syncthreads();
    if (tid < 8) {
        atomicAdd(&d_gsum[inst * 8 + tid], gsh[tid]);
        atomicAdd(&d_gss[inst * 8 + tid], gqh[tid]);
    }
}

// ---- gout(pass0, GN2-fused) + gin(pass1) fused ----------------------------
__global__ void __launch_bounds__(256) k_goutgin(const float* __restrict__ h, const float* __restrict__ wt,
                                                 const float* __restrict__ b, const float* __restrict__ dX,
                                                 const float* __restrict__ cbuf, const float* __restrict__ gsc,
                                                 const float* __restrict__ gbi, int inst,
                                                 const float* __restrict__ zw, const float* __restrict__ ft,
                                                 const float* __restrict__ wg, const float* __restrict__ bg,
                                                 float* __restrict__ k1out, float* __restrict__ hout) {
    __shared__ __align__(16) float w[32 * 64 + 64 + 64 + 128 * 32 + 32];
    int tid = threadIdx.x;
    for (int i = tid; i < 32 * 64; i += 256) w[i] = wt[i];
    if (tid < 64) w[32 * 64 + tid] = b[tid];
    if (tid < 32) w[32 * 64 + 64 + tid] = __ldg(&gsc[tid]);
    if (tid >= 32 && tid < 64) w[32 * 64 + 64 + tid] = __ldg(&gbi[tid - 32]);
    float* wgs = w + 32 * 64 + 64 + 64;
    for (int i = tid; i < 128 * 32; i += 256) wgs[i] = wg[i];
    if (tid < 32) wgs[128 * 32 + tid] = bg[tid];
    __syncthreads();
    const uint64_t* w64 = (const uint64_t*)w;
    const uint64_t* b64 = (const uint64_t*)(w + 32 * 64);
    const float* scv = w + 32 * 64 + 64;
    const float* biv = scv + 32;
    const uint64_t* wg64 = (const uint64_t*)wgs;
    const uint64_t* bg64 = (const uint64_t*)(wgs + 128 * 32);
    float mg[8], rg[8];
    float inv = 1.f / (4.f * (float)NV);
#pragma unroll
    for (int g = 0; g < 8; g++) {
        float m = d_gsum[inst * 8 + g] * inv;
        float var = d_gss[inst * 8 + g] * inv - m * m;
        mg[g] = m;
        rg[g] = rsqrtf(var + 1e-5f);
    }
    int v = blockIdx.x * 256 + tid;
    uint64_t acc[32];
#pragma unroll
    for (int j = 0; j < 32; j++) acc[j] = b64[j];
#pragma unroll 1
    for (int ci = 0; ci < 32; ci++) {
        int g = ci >> 2;
        float cv = cbuf[ci * NV + v];
        float gnv = fmaxf((cv - mg[g]) * rg[g] * scv[ci] + biv[ci], 0.f);
        float val = h[ci * NV + v] + gnv;
        uint64_t vd = dup2(val);
#pragma unroll
        for (int j = 0; j < 32; j++) ffma2(acc[j], w64[ci * 32 + j], vd);
    }
    uint64_t gacc[16];
#pragma unroll
    for (int j = 0; j < 16; j++) gacc[j] = bg64[j];
#pragma unroll 1
    for (int j = 0; j < 32; j++) {
        float2 u = unpack2(acc[j]);
        int i0 = (2 * j) * NV + v, i1 = (2 * j + 1) * NV + v;
        float t0 = tanh_ap(u.x) * dX[i0];
        float t1 = tanh_ap(u.y) * dX[i1];
        k1out[i0] = t0;
        k1out[i1] = t1;
        float a0 = zw[i0] + t0;
        float a1 = zw[i1] + t1;
        uint64_t vd0 = dup2(a0), vd1 = dup2(a1);
#pragma unroll
        for (int jj = 0; jj < 16; jj++) {
            ffma2(gacc[jj], wg64[(2 * j) * 16 + jj], vd0);
            ffma2(gacc[jj], wg64[(2 * j + 1) * 16 + jj], vd1);
        }
    }
#pragma unroll 1
    for (int c = 64; c < 128; c++) {
        float val = __ldg(&ft[(c - 64) * NV + v]);
        uint64_t vd = dup2(val);
#pragma unroll
        for (int jj = 0; jj < 16; jj++) ffma2(gacc[jj], wg64[c * 16 + jj], vd);
    }
#pragma unroll
    for (int jj = 0; jj < 16; jj++) {
        float2 u = unpack2(gacc[jj]);
        hout[(2 * jj) * NV + v] = fmaxf(u.x, 0.f);
        hout[(2 * jj + 1) * NV + v] = fmaxf(u.y, 0.f);
    }
}

// ---- g_out pass1 (GN2-fused, Heun z update) -------------------------------
__global__ void __launch_bounds__(256) k_gout(const float* __restrict__ h, const float* __restrict__ wt,
                                              const float* __restrict__ b, const float* __restrict__ dX,
                                              const float* __restrict__ cbuf, const float* __restrict__ gsc,
                                              const float* __restrict__ gbi, int inst,
                                              const float* __restrict__ zw,
                                              const float* __restrict__ k1in, float* __restrict__ zout) {
    __shared__ __align__(16) float w[32 * 64 + 64 + 64];
    int tid = threadIdx.x;
    for (int i = tid; i < 32 * 64; i += 256) w[i] = wt[i];
    if (tid < 64) w[32 * 64 + tid] = b[tid];
    if (tid < 32) w[32 * 64 + 64 + tid] = __ldg(&gsc[tid]);
    if (tid >= 32 && tid < 64) w[32 * 64 + 64 + tid] = __ldg(&gbi[tid - 32]);
    __syncthreads();
    const uint64_t* w64 = (const uint64_t*)w;
    const uint64_t* b64 = (const uint64_t*)(w + 32 * 64);
    const float* scv = w + 32 * 64 + 64;
    const float* biv = scv + 32;
    float mg[8], rg[8];
    float inv = 1.f / (4.f * (float)NV);
#pragma unroll
    for (int g = 0; g < 8; g++) {
        float m = d_gsum[inst * 8 + g] * inv;
        float var = d_gss[inst * 8 + g] * inv - m * m;
        mg[g] = m;
        rg[g] = rsqrtf(var + 1e-5f);
    }
    int v = blockIdx.x * 256 + tid;
    uint64_t acc[32];
#pragma unroll
    for (int j = 0; j < 32; j++) acc[j] = b64[j];
#pragma unroll 1
    for (int ci = 0; ci < 32; ci++) {
        int g = ci >> 2;
        float cv = cbuf[ci * NV + v];
        float gnv = fmaxf((cv - mg[g]) * rg[g] * scv[ci] + biv[ci], 0.f);
        float val = h[ci * NV + v] + gnv;
        uint64_t vd = dup2(val);
#pragma unroll
        for (int j = 0; j < 32; j++) ffma2(acc[j], w64[ci * 32 + j], vd);
    }
#pragma unroll 1
    for (int j = 0; j < 32; j++) {
        float2 u = unpack2(acc[j]);
        int i0 = (2 * j) * NV + v, i1 = (2 * j + 1) * NV + v;
        float t0 = tanh_ap(u.x) * dX[i0];
        float t1 = tanh_ap(u.y) * dX[i1];
        zout[i0] = zw[i0] + 0.5f * (k1in[i0] + t0);
        zout[i1] = zw[i1] + 0.5f * (k1in[i1] + t1);
    }
}

// ----- decoder: nearest x2 (XY) + conv 64->18 3x3x3 + fast_logits[3] -------
__global__ void __launch_bounds__(144) k_dec(const float* __restrict__ zf,
                                             const float4* __restrict__ wq,
                                             const float* __restrict__ b,
                                             const float* __restrict__ flast,
                                             float* __restrict__ out) {
    extern __shared__ __align__(16) float patch[];
    int tid = threadIdx.x;
    int gx = blockIdx.x / 100, gy = blockIdx.x - gx * 100;
    int x0 = gx * 4, y0 = gy * 2;
    int dx0 = x0 / 2 - 1, dy0 = y0 / 2 - 1;
    for (int u = tid; u < 768; u += 144) {
        int ci = u / 12; int r = u - ci * 12; int dx = r / 3; int dy = r - dx * 3;
        int ddx = dx0 + dx, ddy = dy0 + dy;
        float* col = patch + u * 20;
        if ((unsigned)ddx < (unsigned)Xd && (unsigned)ddy < (unsigned)Yd) {
            const float4* g = (const float4*)(zf + (size_t)ci * NV + (ddx * Yd + ddy) * Zd);
            float4 a0 = g[0], a1 = g[1], a2 = g[2], a3 = g[3];
            col[0] = 0.f;
            col[1] = a0.x; col[2] = a0.y; col[3] = a0.z; col[4] = a0.w;
            col[5] = a1.x; col[6] = a1.y; col[7] = a1.z; col[8] = a1.w;
            col[9] = a2.x; col[10] = a2.y; col[11] = a2.z; col[12] = a2.w;
            col[13] = a3.x; col[14] = a3.y; col[15] = a3.z; col[16] = a3.w;
            col[17] = 0.f;
        } else {
            float4 zz = make_float4(0.f, 0.f, 0.f, 0.f);
            float4* c4 = (float4*)col;
            c4[0] = zz; c4[1] = zz; c4[2] = zz; c4[3] = zz; c4[4] = zz;
        }
    }
    __syncthreads();
    int colid = tid / 18, co = tid - colid * 18;
    int lx = colid >> 1, ly = colid & 1;
    int x = x0 + lx, y = y0 + ly;
    int par = (lx & 1) * 2 + ly;
    int ux = ((x - 1) >> 1) - dx0;
    int vy = ((y - 1) >> 1) - dy0;
    float bb = __ldg(&b[co]);
    uint64_t acc[8];
    uint64_t binit = dup2(bb);
#pragma unroll
    for (int i = 0; i < 8; i++) acc[i] = binit;
#pragma unroll 1
    for (int ci = 0; ci < 64; ci++) {
#pragma unroll
        for (int tap = 0; tap < 4; tap++) {
            int du = tap >> 1, dv = tap & 1;
            const float* col = patch + (ci * 12 + (ux + du) * 3 + (vy + dv)) * 20;
            const ulonglong2* v2 = (const ulonglong2*)col;
            uint64_t pe[9];
            ulonglong2 t0 = v2[0], t1 = v2[1], t2 = v2[2], t3 = v2[3];
            pe[0] = t0.x; pe[1] = t0.y; pe[2] = t1.x; pe[3] = t1.y;
            pe[4] = t2.x; pe[5] = t2.y; pe[6] = t3.x; pe[7] = t3.y;
            pe[8] = ((const uint64_t*)col)[8];
            float4 w = __ldg(&wq[((par * 64 + ci) * 4 + tap) * 18 + co]);
            uint64_t w0 = dup2(w.x), w1 = dup2(w.y), w2 = dup2(w.z);
#pragma unroll
            for (int i = 0; i < 8; i++) ffma2(acc[i], pe[i], w0);
#pragma unroll
            for (int i = 0; i < 8; i++) {
                uint64_t sh = pack2(hi2(pe[i]), lo2(pe[i + 1]));
                ffma2(acc[i], sh, w1);
            }
#pragma unroll
            for (int i = 0; i < 8; i++) ffma2(acc[i], pe[i + 1], w2);
        }
    }
    int ob = co * NVF + (x * Y + y) * Z;
#pragma unroll
    for (int q = 0; q < 4; q++) {
        float2 u0 = unpack2(acc[2 * q]);
        float2 u1 = unpack2(acc[2 * q + 1]);
        out[ob + 4 * q + 0] = u0.x + __ldg(&flast[ob + 4 * q + 0]);
        out[ob + 4 * q + 1] = u0.y + __ldg(&flast[ob + 4 * q + 1]);
        out[ob + 4 * q + 2] = u1.x + __ldg(&flast[ob + 4 * q + 2]);
        out[ob + 4 * q + 3] = u1.y + __ldg(&flast[ob + 4 * q + 3]);
    }
}

// --------------------------------- host ------------------------------------
static void* sym_addr(const void* s) { void* p = nullptr; cudaGetSymbolAddress(&p, s); return p; }

extern "C" void kernel_launch(void* const* d_in, const int* in_sizes, int n_in,
                              void* d_out, int out_size) {
    (void)in_sizes; (void)n_in; (void)out_size;
    const float* fast_logits = (const float*)d_in[0];
    const float* slow_logits = (const float*)d_in[1];
    const float* pose   = (const float*)d_in[2];
    const float* fe_w   = (const float*)d_in[3];
    const float* fe_b   = (const float*)d_in[4];
    const float* se_w   = (const float*)d_in[5];
    const float* se_b   = (const float*)d_in[6];
    const float* ctrl_w = (const float*)d_in[7];
    const float* ctrl_b = (const float*)d_in[8];
    const float* gin_w  = (const float*)d_in[9];
    const float* gin_b  = (const float*)d_in[10];
    const float* gbw    = (const float*)d_in[11];
    const float* gbb    = (const float*)d_in[12];
    const float* gns    = (const float*)d_in[13];
    const float* gnb    = (const float*)d_in[14];
    const float* gout_w = (const float*)d_in[15];
    const float* gout_b = (const float*)d_in[16];
    const float* dec_w  = (const float*)d_in[17];
    const float* dec_b  = (const float*)d_in[18];
    const int*   ts     = (const int*)d_in[19];
    float* out = (float*)d_out;

    float*  p_fast  = (float*)sym_addr(d_fast);
    float*  p_z     = (float*)sym_addr(d_z);
    float*  p_zw    = (float*)sym_addr(d_zw);
    float*  p_dX    = (float*)sym_addr(d_dX);
    float*  p_k1    = (float*)sym_addr(d_k1);
    float*  p_h     = (float*)sym_addr(d_h);
    float*  p_h2    = (float*)sym_addr(d_h2);
    float*  p_c     = (float*)sym_addr(d_c);
    float*  p_c2    = (float*)sym_addr(d_c2);
    float4* p_wfe4  = (float4*)sym_addr(d_wfe4);
    float4* p_wse4  = (float4*)sym_addr(d_wse4);
    float4* p_wbA   = (float4*)sym_addr(d_wbA);
    float2* p_wbB   = (float2*)sym_addr(d_wbB);
    float4* p_wdecv = (float4*)sym_addr(d_wdecv);
    float*  p_wctrl = (float*)sym_addr(d_wctrl);
    float*  p_wgin  = (float*)sym_addr(d_wgin);
    float*  p_wgout = (float*)sym_addr(d_wgout);

    const int SM1 = 3 * 8 * 10 * 20 * 4;   // 19200
    const int SM2 = 3 * 8 * 12 * 20 * 4;   // 23040
    const int SM3 = 3 * 8 * 14 * 24 * 4;   // 32256
    const int SMD = 768 * 20 * 4;          // 61440
    cudaFuncSetAttribute(k_body<1>, cudaFuncAttributeMaxDynamicSharedMemorySize, SM1);
    cudaFuncSetAttribute(k_body<2>, cudaFuncAttributeMaxDynamicSharedMemorySize, SM2);
    cudaFuncSetAttribute(k_body<3>, cudaFuncAttributeMaxDynamicSharedMemorySize, SM3);
    cudaFuncSetAttribute(k_dec, cudaFuncAttributeMaxDynamicSharedMemorySize, SMD);

    k_prep<<<248, 256>>>(fe_w, se_w, gbw, dec_w, ctrl_w, gin_w, gout_w, pose, ts);   // 0
    k_enc<<<dim3(NCOLS / 2, 4), 128>>>(fast_logits, p_wfe4, fe_b, p_fast, nullptr);  // 1
    k_enc<<<dim3(NCOLS / 2, 1), 128>>>(slow_logits, p_wse4, se_b, p_z, p_fast);      // 2

    for (int k = 0; k < 3; k++) {
        const float* fk  = p_fast + (size_t)k * 64 * NV;
        const float* fk1 = p_fast + (size_t)(k + 1) * 64 * NV;
        // launch 3 (k=0): fused warp + ctrl + gin(pass0)  → profiled slot
        k_wcg<<<NV / 128, 128>>>(p_z, fk, fk1, p_wctrl, ctrl_b, p_wgin, gin_b,
                                 p_zw, p_dX, p_h, k);
        int inst0 = k * 6;
        // ---- pass 0 ----
        k_body<1><<<1300, 128, SM1>>>(p_h, nullptr, nullptr, nullptr, nullptr, 0,
                                      p_wbA, p_wbB, gbb, p_c, inst0);
        k_body<2><<<1300, 128, SM2>>>(p_h, p_c, p_h2, gns, gnb, inst0,
                                      p_wbA + 4608, p_wbB + 4608, gbb + 32, p_c2, inst0 + 1);
        k_body<3><<<1300, 128, SM3>>>(p_h2, p_c2, p_h, gns + 32, gnb + 32, inst0 + 1,
                                      p_wbA + 2 * 4608, p_wbB + 2 * 4608, gbb + 64, p_c, inst0 + 2);
        k_goutgin<<<NV / 256, 256>>>(p_h, p_wgout, gout_b, p_dX,
                                     p_c, gns + 64, gnb + 64, inst0 + 2,
                                     p_zw, fk1, p_wgin, gin_b, p_k1, p_h);
        // ---- pass 1 ----
        int inst1 = inst0 + 3;
        k_body<1><<<1300, 128, SM1>>>(p_h, nullptr, nullptr, nullptr, nullptr, 0,
                                      p_wbA, p_wbB, gbb, p_c, inst1);
        k_body<2><<<1300, 128, SM2>>>(p_h, p_c, p_h2, gns, gnb, inst1,
                                      p_wbA + 4608, p_wbB + 4608, gbb + 32, p_c2, inst1 + 1);
        k_body<3><<<1300, 128, SM3>>>(p_h2, p_c2, p_h, gns + 32, gnb + 32, inst1 + 1,
                                      p_wbA + 2 * 4608, p_wbB + 2 * 4608, gbb + 64, p_c, inst1 + 2);
        k_gout<<<NV / 256, 256>>>(p_h, p_wgout, gout_b, p_dX,
                                  p_c, gns + 64, gnb + 64, inst1 + 2,
                                  p_zw, p_k1, p_z);
    }
    k_dec<<<5000, 144, SMD>>>(p_z, p_wdecv, dec_b, fast_logits + (size_t)3 * CL * NVF, out);
}